// round 3
// baseline (speedup 1.0000x reference)
#include <cuda_runtime.h>
#include <cuda_bf16.h>

// SparseConv1dNeq: fake-quant(in) -> masked sparse conv1d (fan-in 8, pad 1) -> fake-quant(out)
// x:      [512, 64, 1024] f32   (d_in[0])
// weight: [64, 64, 3]     f32   (d_in[1])
// mask:   [64, 64, 3]     f32   (d_in[2], exactly 8 ones per out channel)
// out:    [512, 64, 1024] f32

#define BATCH   512
#define IN_CH   64
#define OUT_CH  64
#define KW      3
#define LEN     1024
#define FAN_IN  8

#define TILE_T  128
#define TPAD    (TILE_T + 2)   // halo of 1 on each side (padding=1)
#define NTHREADS 256

#define IN_SCALE_INV  16.0f     // 1/0.0625
#define IN_SCALE      0.0625f
#define OUT_SCALE_INV 8.0f      // 1/0.125
#define OUT_SCALE     0.125f

// Compacted sparse taps: per out channel, 8 (smem-offset, weight) pairs.
__device__ int   g_off[OUT_CH * FAN_IN];
__device__ float g_w  [OUT_CH * FAN_IN];

__global__ void prep_taps_kernel(const float* __restrict__ weight,
                                 const float* __restrict__ mask) {
    int o = threadIdx.x;
    if (o >= OUT_CH) return;
    int cnt = 0;
    #pragma unroll 1
    for (int ic = 0; ic < IN_CH; ic++) {
        #pragma unroll
        for (int k = 0; k < KW; k++) {
            int idx = (o * IN_CH + ic) * KW + k;
            float m = mask[idx];
            if (m != 0.0f && cnt < FAN_IN) {
                // output position t (local tloc) reads smem col tloc + k of channel ic
                g_off[o * FAN_IN + cnt] = ic * TPAD + k;
                g_w  [o * FAN_IN + cnt] = weight[idx] * m;
                cnt++;
            }
        }
    }
    for (; cnt < FAN_IN; cnt++) {
        g_off[o * FAN_IN + cnt] = 0;
        g_w  [o * FAN_IN + cnt] = 0.0f;
    }
}

__device__ __forceinline__ float fq_in(float v) {
    // clip(rint(v/s), -128, 127) * s ; rintf = ties-to-even, matches jnp.round
    return fminf(fmaxf(rintf(v * IN_SCALE_INV), -128.0f), 127.0f) * IN_SCALE;
}
__device__ __forceinline__ float fq_out(float v) {
    return fminf(fmaxf(rintf(v * OUT_SCALE_INV), -128.0f), 127.0f) * OUT_SCALE;
}

__global__ __launch_bounds__(NTHREADS)
void sparse_conv1d_kernel(const float* __restrict__ x,
                          float* __restrict__ out) {
    __shared__ float xs[IN_CH * TPAD];   // 64 * 130 * 4B = 33,280 B

    const int blk  = blockIdx.x;
    const int n    = blk >> 3;           // 1024/128 = 8 tiles per sample
    const int tile = blk & 7;
    const int t0   = tile * TILE_T;

    const float* xn = x + (size_t)n * IN_CH * LEN;

    // ---- Load + input fake-quant into smem (each HBM element read once) ----
    #pragma unroll 4
    for (int i = threadIdx.x; i < IN_CH * TPAD; i += NTHREADS) {
        int ic = i / TPAD;
        int j  = i - ic * TPAD;
        int g  = t0 - 1 + j;             // global position, pad=1
        float v = 0.0f;
        if (g >= 0 && g < LEN) {
            v = fq_in(xn[ic * LEN + g]);
        }
        xs[i] = v;
    }
    __syncthreads();

    // ---- Compute: warp w handles out channels [w*8, w*8+8) over 128 positions ----
    const int warp = threadIdx.x >> 5;
    const int lane = threadIdx.x & 31;
    float* outn = out + (size_t)n * OUT_CH * LEN + t0;

    #pragma unroll 1
    for (int oi = 0; oi < 8; oi++) {
        const int o = warp * 8 + oi;

        int   off[FAN_IN];
        float w  [FAN_IN];
        #pragma unroll
        for (int i = 0; i < FAN_IN; i++) {
            off[i] = g_off[o * FAN_IN + i];
            w  [i] = g_w  [o * FAN_IN + i];
        }

        float* orow = outn + (size_t)o * LEN;
        #pragma unroll
        for (int c = 0; c < TILE_T / 32; c++) {
            const int t = c * 32 + lane;       // lanes stride-1 -> conflict-free LDS, coalesced STG
            float s = 0.0f;
            #pragma unroll
            for (int i = 0; i < FAN_IN; i++) {
                s = fmaf(w[i], xs[off[i] + t], s);
            }
            orow[t] = fq_out(s);
        }
    }
}

extern "C" void kernel_launch(void* const* d_in, const int* in_sizes, int n_in,
                              void* d_out, int out_size) {
    const float* x      = (const float*)d_in[0];
    const float* weight = (const float*)d_in[1];
    const float* mask   = (const float*)d_in[2];
    float*       out    = (float*)d_out;

    prep_taps_kernel<<<1, 64>>>(weight, mask);
    sparse_conv1d_kernel<<<BATCH * (LEN / TILE_T), NTHREADS>>>(x, out);
}

// round 5
// speedup vs baseline: 1.6806x; 1.6806x over previous
#include <cuda_runtime.h>
#include <cuda_bf16.h>

// SparseConv1dNeq: fake-quant(in) -> masked sparse conv1d (fan-in 8, pad 1) -> fake-quant(out)
// x:      [512, 64, 1024] f32   (d_in[0])
// weight: [64, 64, 3]     f32   (d_in[1])
// mask:   [64, 64, 3]     f32   (d_in[2], exactly 8 ones per out channel)
// out:    [512, 64, 1024] f32

#define BATCH   512
#define IN_CH   64
#define OUT_CH  64
#define KW      3
#define LEN     1024
#define FAN_IN  8

#define TILE_T  128
#define ROWSTRIDE 136          // floats per smem row: >= 133 (130 data + base off 3), mult of 4
#define NTHREADS 256

#define IN_SCALE_INV  16.0f    // 1/0.0625
#define IN_SCALE      0.0625f
#define OUT_SCALE_INV 8.0f     // 1/0.125
#define OUT_SCALE     0.125f

// Compacted sparse taps: per out channel, 8 (smem-offset, weight) pairs.
__device__ int   g_off[OUT_CH * FAN_IN];
__device__ float g_w  [OUT_CH * FAN_IN];

// ---------------- Prep: parallel ballot-based tap compaction ----------------
// One block per out channel, 192 threads = one thread per (ic, k) tap.
// Deterministic ordering via warp ballot + block prefix scan.
__global__ void prep_taps_kernel(const float* __restrict__ weight,
                                 const float* __restrict__ mask) {
    const int o   = blockIdx.x;
    const int idx = threadIdx.x;          // 0..191 over (ic*KW + k)
    __shared__ int wcnt[6];
    __shared__ int total;

    float m = mask[o * (IN_CH * KW) + idx];
    bool  p = (m != 0.0f);

    unsigned bal = __ballot_sync(0xffffffffu, p);
    int warp = idx >> 5;
    int lane = idx & 31;
    if (lane == 0) wcnt[warp] = __popc(bal);
    __syncthreads();

    int prefix = 0;
    #pragma unroll
    for (int w = 0; w < 6; w++)
        if (w < warp) prefix += wcnt[w];
    if (idx == 0) {
        int t = 0;
        #pragma unroll
        for (int w = 0; w < 6; w++) t += wcnt[w];
        total = t;
    }
    int rank = prefix + __popc(bal & ((1u << lane) - 1u));
    __syncthreads();

    if (p && rank < FAN_IN) {
        int ic = idx / KW;
        int k  = idx - ic * KW;
        // compute loop reads xs[off + t]; xs[r*ROWSTRIDE + 3 + j] holds g = t0-1+j,
        // and output t needs g = t0 + t + k - 1  =>  off = ic*ROWSTRIDE + 3 + k
        g_off[o * FAN_IN + rank] = ic * ROWSTRIDE + 3 + k;
        g_w  [o * FAN_IN + rank] = weight[o * (IN_CH * KW) + idx] * m;
    }
    // zero-fill tail if fewer than FAN_IN taps (shouldn't happen, but safe)
    if (idx < FAN_IN && idx >= total) {
        g_off[o * FAN_IN + idx] = 0;
        g_w  [o * FAN_IN + idx] = 0.0f;
    }
}

__device__ __forceinline__ float fq_in(float v) {
    return fminf(fmaxf(rintf(v * IN_SCALE_INV), -128.0f), 127.0f) * IN_SCALE;
}
__device__ __forceinline__ float fq_out(float v) {
    return fminf(fmaxf(rintf(v * OUT_SCALE_INV), -128.0f), 127.0f) * OUT_SCALE;
}

// ---------------- Main kernel ----------------
__global__ __launch_bounds__(NTHREADS)
void sparse_conv1d_kernel(const float* __restrict__ x,
                          float* __restrict__ out) {
    __shared__ float xs[IN_CH * ROWSTRIDE];   // 64 * 136 * 4B = 34,816 B

    const int blk  = blockIdx.x;
    const int n    = blk >> 3;                // 8 tiles of 128 per sample
    const int tile = blk & 7;
    const int t0   = tile * TILE_T;

    const float* xn = x + (size_t)n * IN_CH * LEN;
    const int tid = threadIdx.x;

    // ---- Body load: 64 rows x 128 positions as float4 (coalesced, high MLP) ----
    // smem row r holds g = t0-1+j at xs[r*ROWSTRIDE + 3 + j]; body j = 1..128.
    #pragma unroll
    for (int it = 0; it < 8; it++) {
        int v = tid + it * NTHREADS;          // 0..2047
        int r = v >> 5;                       // row (in channel)
        int m = v & 31;                       // float4 index within row
        const float4 q = *reinterpret_cast<const float4*>(xn + r * LEN + t0 + m * 4);
        float4 s;
        s.x = fq_in(q.x); s.y = fq_in(q.y); s.z = fq_in(q.z); s.w = fq_in(q.w);
        *reinterpret_cast<float4*>(&xs[r * ROWSTRIDE + 4 + m * 4]) = s;
    }
    // ---- Halos: j=0 (g=t0-1) by threads [0,64), j=129 (g=t0+128) by [128,192) ----
    if (tid < IN_CH) {
        int r = tid;
        float v = 0.0f;
        if (t0 > 0) v = fq_in(xn[r * LEN + t0 - 1]);
        xs[r * ROWSTRIDE + 3] = v;
    } else if (tid >= 128 && tid < 128 + IN_CH) {
        int r = tid - 128;
        float v = 0.0f;
        if (t0 + TILE_T < LEN) v = fq_in(xn[r * LEN + t0 + TILE_T]);
        xs[r * ROWSTRIDE + 3 + 129] = v;
    }
    __syncthreads();

    // ---- Compute: warp w handles out channels [w*8, w*8+8) over 128 positions ----
    const int warp = tid >> 5;
    const int lane = tid & 31;
    float* outn = out + (size_t)n * OUT_CH * LEN + t0;

    #pragma unroll 1
    for (int oi = 0; oi < 8; oi++) {
        const int o = warp * 8 + oi;

        int   off[FAN_IN];
        float w  [FAN_IN];
        #pragma unroll
        for (int i = 0; i < FAN_IN; i++) {
            off[i] = g_off[o * FAN_IN + i];
            w  [i] = g_w  [o * FAN_IN + i];
        }

        float* orow = outn + (size_t)o * LEN;
        #pragma unroll
        for (int c = 0; c < TILE_T / 32; c++) {
            const int t = c * 32 + lane;
            // dual accumulators -> 16-cycle dep chain instead of 32
            float s0 = 0.0f, s1 = 0.0f;
            #pragma unroll
            for (int i = 0; i < FAN_IN; i += 2) {
                s0 = fmaf(w[i],     xs[off[i]     + t], s0);
                s1 = fmaf(w[i + 1], xs[off[i + 1] + t], s1);
            }
            orow[t] = fq_out(s0 + s1);
        }
    }
}

extern "C" void kernel_launch(void* const* d_in, const int* in_sizes, int n_in,
                              void* d_out, int out_size) {
    const float* x      = (const float*)d_in[0];
    const float* weight = (const float*)d_in[1];
    const float* mask   = (const float*)d_in[2];
    float*       out    = (float*)d_out;

    prep_taps_kernel<<<OUT_CH, IN_CH * KW>>>(weight, mask);
    sparse_conv1d_kernel<<<BATCH * (LEN / TILE_T), NTHREADS>>>(x, out);
}

// round 8
// speedup vs baseline: 1.8440x; 1.0973x over previous
#include <cuda_runtime.h>
#include <cuda_fp16.h>

// SparseConv1dNeq: fake-quant(in) -> masked sparse conv1d (fan-in 8, pad 1) -> fake-quant(out)
// x:      [512, 64, 1024] f32   (d_in[0])
// weight: [64, 64, 3]     f32   (d_in[1])
// mask:   [64, 64, 3]     f32   (d_in[2], exactly 8 ones per out channel)
// out:    [512, 64, 1024] f32
//
// Quantized inputs (q * 0.0625, q in [-128,127]) are EXACTLY representable in fp16,
// so smem stores half: one LDS.32 = 2 positions -> half the LDS wavefronts.
// Two smem copies at a 1-position shift make every tap (k=0,1,2) an aligned half2 read.

#define BATCH   512
#define IN_CH   64
#define OUT_CH  64
#define KW      3
#define LEN     1024
#define FAN_IN  8

#define TILE_T  128
#define ROW_H   136            // halfs per smem row (272 B)
#define ROW_W   68             // 32-bit words per row
#define B_BASE_W (IN_CH * ROW_W)   // word offset of copy B = 4352
#define NTHREADS 256

#define IN_SCALE_INV  16.0f
#define IN_SCALE      0.0625f
#define OUT_SCALE_INV 8.0f
#define OUT_SCALE     0.125f

// Compacted sparse taps: per out channel, 8 (smem word-offset, f32 weight) pairs.
__device__ int   g_off[OUT_CH * FAN_IN];
__device__ float g_w  [OUT_CH * FAN_IN];

// ---------------- Prep: parallel ballot-based tap compaction ----------------
__global__ void prep_taps_kernel(const float* __restrict__ weight,
                                 const float* __restrict__ mask) {
    const int o   = blockIdx.x;
    const int idx = threadIdx.x;          // 0..191 over (ic*KW + k)
    __shared__ int wcnt[6];
    __shared__ int total;

    float m = mask[o * (IN_CH * KW) + idx];
    bool  p = (m != 0.0f);

    unsigned bal = __ballot_sync(0xffffffffu, p);
    int warp = idx >> 5;
    int lane = idx & 31;
    if (lane == 0) wcnt[warp] = __popc(bal);
    __syncthreads();

    int prefix = 0;
    #pragma unroll
    for (int w = 0; w < 6; w++)
        if (w < warp) prefix += wcnt[w];
    if (idx == 0) {
        int t = 0;
        #pragma unroll
        for (int w = 0; w < 6; w++) t += wcnt[w];
        total = t;
    }
    int rank = prefix + __popc(bal & ((1u << lane) - 1u));
    __syncthreads();

    if (p && rank < FAN_IN) {
        int ic = idx / KW;
        int k  = idx - ic * KW;
        // Compute reads word[off + l], l = local pair index (positions 2l, 2l+1).
        // Copy A: position p at half idx 4+p        -> k=1 pair starts at word ic*68+2+l
        // Copy B: position p at half idx 5+p        -> k=0 pair (2l-1,2l)  at B + ic*68+2+l
        //                                              k=2 pair (2l+1,2l+2) at B + ic*68+3+l
        int off;
        if (k == 1)      off = ic * ROW_W + 2;
        else if (k == 0) off = B_BASE_W + ic * ROW_W + 2;
        else             off = B_BASE_W + ic * ROW_W + 3;
        g_off[o * FAN_IN + rank] = off;
        g_w  [o * FAN_IN + rank] = weight[o * (IN_CH * KW) + idx] * m;
    }
    if (idx < FAN_IN && idx >= total) {
        g_off[o * FAN_IN + idx] = 0;
        g_w  [o * FAN_IN + idx] = 0.0f;
    }
}

__device__ __forceinline__ float fq_in(float v) {
    return fminf(fmaxf(rintf(v * IN_SCALE_INV), -128.0f), 127.0f) * IN_SCALE;
}
__device__ __forceinline__ float fq_out(float v) {
    return fminf(fmaxf(rintf(v * OUT_SCALE_INV), -128.0f), 127.0f) * OUT_SCALE;
}

__device__ __forceinline__ unsigned pack2(float a, float b) {
    __half2 h = __floats2half2_rn(a, b);   // exact: values have <=8 significant bits
    return *reinterpret_cast<unsigned*>(&h);
}

// ---------------- Main kernel ----------------
__global__ __launch_bounds__(NTHREADS)
void sparse_conv1d_kernel(const float* __restrict__ x,
                          float* __restrict__ out) {
    // Copy A (positions 0..127 of tile at half idx 4+p) then copy B (shifted by 1).
    __shared__ __half xs[2 * IN_CH * ROW_H];   // 34,816 B
    unsigned* xsw = reinterpret_cast<unsigned*>(xs);

    const int blk  = blockIdx.x;
    const int n    = blk >> 3;
    const int tile = blk & 7;
    const int t0   = tile * TILE_T;

    const float* xn = x + (size_t)n * IN_CH * LEN;
    const int tid  = threadIdx.x;
    const int lane = tid & 31;

    // ---- Load: float4 per thread (4 positions), quant, pack fp16, write A + B ----
    #pragma unroll
    for (int it = 0; it < 8; it++) {
        int v = tid + it * NTHREADS;          // 0..2047
        int r = v >> 5;                       // channel row (uniform across warp)
        int m = v & 31;                       // quad index == lane
        const float4 q = *reinterpret_cast<const float4*>(xn + r * LEN + t0 + m * 4);
        float f0 = fq_in(q.x), f1 = fq_in(q.y), f2 = fq_in(q.z), f3 = fq_in(q.w);
        unsigned lo = pack2(f0, f1);          // (h0,h1)
        unsigned hi = pack2(f2, f3);          // (h2,h3)

        // A: positions 4m..4m+3 at half idx 4+4m -> word idx r*68 + 2 + 2m (8B aligned)
        *reinterpret_cast<uint2*>(&xsw[r * ROW_W + 2 + 2 * m]) = make_uint2(lo, hi);

        // B: shifted copy. word (h1,h2) at half idx 6+4m -> word B + r*68 + 3 + 2m
        unsigned mid = __byte_perm(lo, hi, 0x5432);
        xsw[B_BASE_W + r * ROW_W + 3 + 2 * m] = mid;
        // word (h3, next quad's h0) at half idx 8+4m -> word B + r*68 + 4 + 2m
        unsigned nlo = __shfl_down_sync(0xffffffffu, lo, 1);
        if (m != 31) {
            xsw[B_BASE_W + r * ROW_W + 4 + 2 * m] = __byte_perm(hi, nlo, 0x5432);
        }
    }
    // ---- Halos (copy B only; copy A needs none) ----
    if (tid < IN_CH) {
        int r = tid;
        float a = (t0 > 0) ? fq_in(xn[r * LEN + t0 - 1]) : 0.0f;
        float b = fq_in(xn[r * LEN + t0]);
        xsw[B_BASE_W + r * ROW_W + 2] = pack2(a, b);          // positions (-1, 0), half idx 4
    } else if (tid >= 128 && tid < 128 + IN_CH) {
        int r = tid - 128;
        float a = fq_in(xn[r * LEN + t0 + TILE_T - 1]);
        float b = (t0 + TILE_T < LEN) ? fq_in(xn[r * LEN + t0 + TILE_T]) : 0.0f;
        xsw[B_BASE_W + r * ROW_W + 2 + TILE_T / 2] = pack2(a, b);  // positions (127, 128)
    }
    __syncthreads();

    // ---- Compute: warp w -> out channels [w*8, w*8+8), 2 positions per lane ----
    const int warp = tid >> 5;
    float* outn = out + (size_t)n * OUT_CH * LEN + t0;

    #pragma unroll 1
    for (int oi = 0; oi < 8; oi++) {
        const int o = warp * 8 + oi;

        int   off[FAN_IN];
        float w  [FAN_IN];
        #pragma unroll
        for (int i = 0; i < FAN_IN; i++) {
            off[i] = g_off[o * FAN_IN + i];
            w  [i] = g_w  [o * FAN_IN + i];
        }

        float* orow = outn + (size_t)o * LEN;
        #pragma unroll
        for (int c = 0; c < 2; c++) {
            const int l = c * 32 + lane;       // pair index: positions (2l, 2l+1)
            float ax = 0.0f, ay = 0.0f, bx = 0.0f, by = 0.0f;
            #pragma unroll
            for (int i = 0; i < FAN_IN; i += 2) {
                unsigned p0 = xsw[off[i]     + l];
                unsigned p1 = xsw[off[i + 1] + l];
                float2 f0 = __half22float2(*reinterpret_cast<__half2*>(&p0));
                float2 f1 = __half22float2(*reinterpret_cast<__half2*>(&p1));
                ax = fmaf(w[i],     f0.x, ax);
                ay = fmaf(w[i],     f0.y, ay);
                bx = fmaf(w[i + 1], f1.x, bx);
                by = fmaf(w[i + 1], f1.y, by);
            }
            float2 r;
            r.x = fq_out(ax + bx);
            r.y = fq_out(ay + by);
            *reinterpret_cast<float2*>(orow + 2 * l) = r;   // STG.64 coalesced
        }
    }
}

extern "C" void kernel_launch(void* const* d_in, const int* in_sizes, int n_in,
                              void* d_out, int out_size) {
    const float* x      = (const float*)d_in[0];
    const float* weight = (const float*)d_in[1];
    const float* mask   = (const float*)d_in[2];
    float*       out    = (float*)d_out;

    prep_taps_kernel<<<OUT_CH, IN_CH * KW>>>(weight, mask);
    sparse_conv1d_kernel<<<BATCH * (LEN / TILE_T), NTHREADS>>>(x, out);
}